// round 5
// baseline (speedup 1.0000x reference)
#include <cuda_runtime.h>
#include <cuda_bf16.h>

// 256 elems per 256-thread block. All global traffic is perfectly coalesced
// LDG.128 / STG.128 via shared-memory AoS staging; fits a 32-register budget.
constexpr int TPB = 256;
constexpr int EPB = 256;

struct Cov6 { float c00, c01, c02, c11, c12, c22; };

__device__ __forceinline__ Cov6 cov_elem(float sraw0, float sraw1, float sraw2, float4 q)
{
    // s^2 = exp(2*raw): squaring folded into exponent
    float s0 = __expf(2.0f * sraw0);
    float s1 = __expf(2.0f * sraw1);
    float s2 = __expf(2.0f * sraw2);

    float inv = rsqrtf(q.x * q.x + q.y * q.y + q.z * q.z + q.w * q.w);
    float w = q.x * inv, x = q.y * inv, y = q.z * inv, z = q.w * inv;

    float r00 = 1.0f - 2.0f * (y * y + z * z);
    float r01 = 2.0f * (x * y - w * z);
    float r02 = 2.0f * (x * z + w * y);
    float r10 = 2.0f * (x * y + w * z);
    float r11 = 1.0f - 2.0f * (x * x + z * z);
    float r12 = 2.0f * (y * z - w * x);
    float r20 = 2.0f * (x * z - w * y);
    float r21 = 2.0f * (y * z + w * x);
    float r22 = 1.0f - 2.0f * (x * x + y * y);

    Cov6 c;
    c.c00 = r00 * r00 * s0 + r01 * r01 * s1 + r02 * r02 * s2;
    c.c01 = r00 * r10 * s0 + r01 * r11 * s1 + r02 * r12 * s2;
    c.c02 = r00 * r20 * s0 + r01 * r21 * s1 + r02 * r22 * s2;
    c.c11 = r10 * r10 * s0 + r11 * r11 * s1 + r12 * r12 * s2;
    c.c12 = r10 * r20 * s0 + r11 * r21 * s1 + r12 * r22 * s2;
    c.c22 = r20 * r20 * s0 + r21 * r21 * s1 + r22 * r22 * s2;
    return c;
}

__global__ __launch_bounds__(TPB)
void gaussian_cov_smem_kernel(const float4* __restrict__ sc4,
                              const float4* __restrict__ rot,
                              float4* __restrict__ out4,
                              int n)
{
    __shared__ float s_in [3 * EPB];  // 3 KB: staged scaling, AoS
    __shared__ float s_out[6 * EPB];  // 6 KB: staged covariance, AoS

    int tid  = threadIdx.x;
    int base = blockIdx.x * EPB;

    if (base + EPB <= n) {
        // ---- Stage scaling: 192 coalesced LDG.128 -> STS.128 ----
        float4 sv;
        bool has_sv = (tid < 3 * EPB / 4);
        if (has_sv) sv = sc4[(size_t)blockIdx.x * (3 * EPB / 4) + tid];
        // Rotation load issued before the sync: second load in flight per thread
        float4 q = rot[base + tid];
        if (has_sv) ((float4*)s_in)[tid] = sv;
        __syncthreads();

        // ---- Compute: stride-3 LDS is bank-conflict-free (gcd(3,32)=1) ----
        Cov6 c = cov_elem(s_in[3 * tid + 0], s_in[3 * tid + 1], s_in[3 * tid + 2], q);

        s_out[6 * tid + 0] = c.c00;
        s_out[6 * tid + 1] = c.c01;
        s_out[6 * tid + 2] = c.c02;
        s_out[6 * tid + 3] = c.c11;
        s_out[6 * tid + 4] = c.c12;
        s_out[6 * tid + 5] = c.c22;
        __syncthreads();

        // ---- Drain: 384 coalesced LDS.128 -> STG.128 ----
        const float4* so = (const float4*)s_out;
        float4* og = out4 + (size_t)blockIdx.x * (6 * EPB / 4);
        og[tid] = so[tid];
        if (tid < 6 * EPB / 4 - TPB)  // remaining 128
            og[TPB + tid] = so[TPB + tid];
    } else {
        // Scalar tail (not hit for N=4M = 15625 * 256)
        int i = base + tid;
        if (i < n) {
            const float* scal = (const float*)sc4;
            float* out = (float*)out4;
            Cov6 c = cov_elem(scal[3 * i + 0], scal[3 * i + 1], scal[3 * i + 2], rot[i]);
            out[6 * i + 0] = c.c00; out[6 * i + 1] = c.c01; out[6 * i + 2] = c.c02;
            out[6 * i + 3] = c.c11; out[6 * i + 4] = c.c12; out[6 * i + 5] = c.c22;
        }
    }
}

extern "C" void kernel_launch(void* const* d_in, const int* in_sizes, int n_in,
                              void* d_out, int out_size)
{
    const float4* sc4 = (const float4*)d_in[0];  // [N,3] float32
    const float4* rot = (const float4*)d_in[1];  // [N,4] float32
    float4*       out = (float4*)d_out;          // [N,6] float32

    int n = in_sizes[0] / 3;  // N elements
    int blocks = (n + EPB - 1) / EPB;
    gaussian_cov_smem_kernel<<<blocks, TPB>>>(sc4, rot, out, n);
}

// round 6
// speedup vs baseline: 1.0333x; 1.0333x over previous
#include <cuda_runtime.h>
#include <cuda_bf16.h>

// Round-1 scalar kernel (empirical best: 29.6us ncu) + streaming stores.
// __stcs marks output lines evict-first in L2, protecting the ~112MB input
// working set's L2 residency (measured: ~46MB of reads already hit L2).
__global__ __launch_bounds__(256)
void gaussian_cov_kernel(const float* __restrict__ scaling,
                         const float4* __restrict__ rot,
                         float2* __restrict__ out,
                         int n)
{
    int i = blockIdx.x * blockDim.x + threadIdx.x;
    if (i >= n) return;

    // s^2 = exp(2*raw); 2*raw as raw+raw (FADD, off the fma pipe's FMUL slot)
    float a0 = scaling[3 * i + 0];
    float a1 = scaling[3 * i + 1];
    float a2 = scaling[3 * i + 2];
    float s0 = __expf(a0 + a0);
    float s1 = __expf(a1 + a1);
    float s2 = __expf(a2 + a2);

    float4 q = rot[i];
    float inv = rsqrtf(q.x * q.x + q.y * q.y + q.z * q.z + q.w * q.w);
    float w = q.x * inv;
    float x = q.y * inv;
    float y = q.z * inv;
    float z = q.w * inv;

    float r00 = 1.0f - 2.0f * (y * y + z * z);
    float r01 = 2.0f * (x * y - w * z);
    float r02 = 2.0f * (x * z + w * y);
    float r10 = 2.0f * (x * y + w * z);
    float r11 = 1.0f - 2.0f * (x * x + z * z);
    float r12 = 2.0f * (y * z - w * x);
    float r20 = 2.0f * (x * z - w * y);
    float r21 = 2.0f * (y * z + w * x);
    float r22 = 1.0f - 2.0f * (x * x + y * y);

    // cov[i][k] = sum_j R[i][j] * R[k][j] * s[j]^2
    float c00 = r00 * r00 * s0 + r01 * r01 * s1 + r02 * r02 * s2;
    float c01 = r00 * r10 * s0 + r01 * r11 * s1 + r02 * r12 * s2;
    float c02 = r00 * r20 * s0 + r01 * r21 * s1 + r02 * r22 * s2;
    float c11 = r10 * r10 * s0 + r11 * r11 * s1 + r12 * r12 * s2;
    float c12 = r10 * r20 * s0 + r11 * r21 * s1 + r12 * r22 * s2;
    float c22 = r20 * r20 * s0 + r21 * r21 * s1 + r22 * r22 * s2;

    // Streaming (evict-first) 64-bit stores: output is write-once, never
    // re-read here — keep it from evicting the input set from L2.
    __stcs(&out[3 * i + 0], make_float2(c00, c01));
    __stcs(&out[3 * i + 1], make_float2(c02, c11));
    __stcs(&out[3 * i + 2], make_float2(c12, c22));
}

extern "C" void kernel_launch(void* const* d_in, const int* in_sizes, int n_in,
                              void* d_out, int out_size)
{
    const float*  scaling = (const float*)d_in[0];   // [N,3] float32
    const float4* rot     = (const float4*)d_in[1];  // [N,4] float32
    float2*       out     = (float2*)d_out;          // [N,6] float32

    int n = in_sizes[0] / 3;  // N
    int threads = 256;
    int blocks = (n + threads - 1) / threads;
    gaussian_cov_kernel<<<blocks, threads>>>(scaling, rot, out, n);
}

// round 9
// speedup vs baseline: 1.0408x; 1.0073x over previous
#include <cuda_runtime.h>
#include <cuda_bf16.h>

// Round-6 load/compute path (best: 28.7us) + output staged through smem and
// drained with 256-bit evict-first streaming stores (st.global.cs.v8.b32).
// Output stream: 192 coalesced STG.256 per block instead of 768 STG.64 —
// ~3x fewer store wavefronts, and .cs keeps the write-once 96MB stream from
// polluting L2 (protecting input residency across graph replays).

constexpr int TPB = 256;

__global__ __launch_bounds__(TPB)
void gaussian_cov_kernel(const float* __restrict__ scaling,
                         const float4* __restrict__ rot,
                         float* __restrict__ out,
                         int n)
{
    __shared__ float s_out[6 * TPB];  // 6 KB staged output

    int tid = threadIdx.x;
    int i = blockIdx.x * TPB + tid;
    bool full_block = (blockIdx.x + 1) * TPB <= n;  // uniform per block

    if (i < n) {
        // ---- proven load path: 3x LDG.32 + 1x LDG.128 ----
        float a0 = scaling[3 * i + 0];
        float a1 = scaling[3 * i + 1];
        float a2 = scaling[3 * i + 2];
        float4 q = rot[i];

        // s^2 = exp(2*raw): squaring folded into exponent
        float s0 = __expf(a0 + a0);
        float s1 = __expf(a1 + a1);
        float s2 = __expf(a2 + a2);

        float inv = rsqrtf(q.x * q.x + q.y * q.y + q.z * q.z + q.w * q.w);
        float w = q.x * inv, x = q.y * inv, y = q.z * inv, z = q.w * inv;

        float r00 = 1.0f - 2.0f * (y * y + z * z);
        float r01 = 2.0f * (x * y - w * z);
        float r02 = 2.0f * (x * z + w * y);
        float r10 = 2.0f * (x * y + w * z);
        float r11 = 1.0f - 2.0f * (x * x + z * z);
        float r12 = 2.0f * (y * z - w * x);
        float r20 = 2.0f * (x * z - w * y);
        float r21 = 2.0f * (y * z + w * x);
        float r22 = 1.0f - 2.0f * (x * x + y * y);

        float c00 = r00 * r00 * s0 + r01 * r01 * s1 + r02 * r02 * s2;
        float c01 = r00 * r10 * s0 + r01 * r11 * s1 + r02 * r12 * s2;
        float c02 = r00 * r20 * s0 + r01 * r21 * s1 + r02 * r22 * s2;
        float c11 = r10 * r10 * s0 + r11 * r11 * s1 + r12 * r12 * s2;
        float c12 = r10 * r20 * s0 + r11 * r21 * s1 + r12 * r22 * s2;
        float c22 = r20 * r20 * s0 + r21 * r21 * s1 + r22 * r22 * s2;

        if (full_block) {
            s_out[6 * tid + 0] = c00;
            s_out[6 * tid + 1] = c01;
            s_out[6 * tid + 2] = c02;
            s_out[6 * tid + 3] = c11;
            s_out[6 * tid + 4] = c12;
            s_out[6 * tid + 5] = c22;
        } else {
            // tail block: direct scalar stores (not hit for N=4M)
            out[6 * i + 0] = c00; out[6 * i + 1] = c01; out[6 * i + 2] = c02;
            out[6 * i + 3] = c11; out[6 * i + 4] = c12; out[6 * i + 5] = c22;
        }
    }

    if (full_block) {
        __syncthreads();
        // Drain 6KB as 192 x 32B coalesced evict-first stores
        if (tid < 6 * TPB / 8) {
            const uint4* so = (const uint4*)s_out;
            uint4 lo = so[2 * tid + 0];
            uint4 hi = so[2 * tid + 1];
            float* gp = out + (size_t)blockIdx.x * (6 * TPB) + tid * 8;
            asm volatile(
                "st.global.cs.v8.b32 [%0], {%1,%2,%3,%4,%5,%6,%7,%8};"
                :: "l"(gp),
                   "r"(lo.x), "r"(lo.y), "r"(lo.z), "r"(lo.w),
                   "r"(hi.x), "r"(hi.y), "r"(hi.z), "r"(hi.w)
                : "memory");
        }
    }
}

extern "C" void kernel_launch(void* const* d_in, const int* in_sizes, int n_in,
                              void* d_out, int out_size)
{
    const float*  scaling = (const float*)d_in[0];   // [N,3] float32
    const float4* rot     = (const float4*)d_in[1];  // [N,4] float32
    float*        out     = (float*)d_out;           // [N,6] float32

    int n = in_sizes[0] / 3;  // N
    int blocks = (n + TPB - 1) / TPB;
    gaussian_cov_kernel<<<blocks, TPB>>>(scaling, rot, out, n);
}